// round 14
// baseline (speedup 1.0000x reference)
#include <cuda_runtime.h>
#include <cuda_fp16.h>

#define DIM 128
#define HEADS 4
#define NMAX 50000
#define BCAP 64
#define OVF_CAP 2048

// ---- device scratch ----
__device__ __half d_hx16[NMAX * 256];    // per node, per lane c: [h(4 halves), x(4 halves)]
__device__ float d_asrc[NMAX * HEADS];
__device__ float d_adst[NMAX * HEADS];
__device__ float d_gacc[NMAX * DIM];     // gat_out (incl b_gat)
__device__ float d_sacc[NMAX * DIM];     // SAGE mean
__device__ float d_B[DIM * DIM];         // W_sage_l @ Wp2
__device__ float d_C[DIM * DIM];         // W_sage_r @ Wp2 + I
__device__ float d_dvec[DIM];            // b_sage_l @ Wp2 + b_proj
__device__ int   d_fill[NMAX];           // zero at module load; re-zeroed by k_final tail
__device__ int   d_esrc[NMAX * BCAP];
__device__ int   d_ovf[OVF_CAP * 2];
__device__ int   d_ovf_cnt;              // zero at module load; re-zeroed by k_final tail

__device__ __forceinline__ void mma_tf32(float c[4], unsigned a0, unsigned a1,
                                         unsigned a2, unsigned a3,
                                         unsigned b0, unsigned b1) {
    asm volatile(
        "mma.sync.aligned.m16n8k8.row.col.f32.tf32.tf32.f32 "
        "{%0,%1,%2,%3}, {%4,%5,%6,%7}, {%8,%9}, {%0,%1,%2,%3};"
        : "+f"(c[0]), "+f"(c[1]), "+f"(c[2]), "+f"(c[3])
        : "r"(a0), "r"(a1), "r"(a2), "r"(a3), "r"(b0), "r"(b1));
}

__device__ __forceinline__ void cp16(void* sptr, const void* g, int srcsize) {
    unsigned sm = (unsigned)__cvta_generic_to_shared(sptr);
    asm volatile("cp.async.cg.shared.global [%0], [%1], 16, %2;"
                 :: "r"(sm), "l"(g), "r"(srcsize));
}
#define CP_COMMIT() asm volatile("cp.async.commit_group;")
#define CP_WAIT_1() asm volatile("cp.async.wait_group 1;")
#define CP_WAIT_0() asm volatile("cp.async.wait_group 0;")

// GEMM branch smem: 32-row A tiles double-buffered + 16-row W tiles double-buffered
struct PipeSmem32 { float a[2][32 * 20]; float w[2][16 * 136]; };
union KSm {
    PipeSmem32 p;
    float ot[32 * 132];
    struct { float xs[64 * 16]; float ws[16 * 128]; } pr;
    int is64;
};

// ===== fused kernel: scatter blocks FIRST, then gemm_h blocks (32 rows), then prep =====
__global__ void k_fused(const float* __restrict__ x, const float* __restrict__ Wg,
                        const float* __restrict__ att_src, const float* __restrict__ att_dst,
                        const int* __restrict__ eidx,
                        const float* __restrict__ Wl, const float* __restrict__ Wr,
                        const float* __restrict__ bl, const float* __restrict__ Wp,
                        const float* __restrict__ bp,
                        int n, int E, int nbG, int nbS) {
    __shared__ KSm u;
    int bid = blockIdx.x;
    int tid = threadIdx.x, lane = tid & 31, wid = tid >> 5;

    if (bid < nbS) {
        // ---------------- scatter branch: 4 edges per thread --------------------------
        const unsigned* eraw = (const unsigned*)eidx;
        if (tid < 32) {
            unsigned v = eraw[2 * tid + 1];
            unsigned ball = __ballot_sync(0xffffffffu, v == 0u);
            if (tid == 0) u.is64 = (ball == 0xffffffffu) ? 1 : 0;
        }
        __syncthreads();
        int is64 = u.is64;
        int t = bid * 256 + tid;
        int base = t * 4;
        if (base >= E) return;
        int m = E - base; if (m > 4) m = 4;
        int s[4], d[4];
        if (is64) {
            const long long* p = (const long long*)eidx;
#pragma unroll
            for (int j = 0; j < 4; j++) if (j < m) {
                s[j] = (int)__ldg(&p[base + j]); d[j] = (int)__ldg(&p[E + base + j]);
            }
        } else {
#pragma unroll
            for (int j = 0; j < 4; j++) if (j < m) {
                s[j] = __ldg(&eidx[base + j]); d[j] = __ldg(&eidx[E + base + j]);
            }
        }
#pragma unroll
        for (int j = 0; j < 4; j++) if (j < m) {
            int slot = atomicAdd(&d_fill[d[j]], 1);
            if (slot < BCAP) {
                d_esrc[d[j] * BCAP + slot] = s[j];
            } else {
                int o = atomicAdd(&d_ovf_cnt, 1);
                if (o < OVF_CAP) { d_ovf[2 * o] = s[j]; d_ovf[2 * o + 1] = d[j]; }
            }
        }
    } else if (bid < nbS + nbG) {
        // -------- GEMM1 branch (32 rows/block): h = x @ W_gat + logits + hx16 --------
        int rowBase = (bid - nbS) * 32;
        int warpM = wid & 1, warpN = wid >> 1;         // 2 x 4 warp grid, 16x32 per warp
        int g = lane >> 2, tig = lane & 3;
        int r = tid >> 2, c4 = (tid & 3) << 2;         // threads 0..127 stage A rows 0..31
        int gr = rowBase + r;
        bool stagerA = (tid < 128);

        if (stagerA)
            cp16(&u.p.a[0][r * 20 + c4], &x[(size_t)gr * DIM + c4], gr < n ? 16 : 0);
#pragma unroll
        for (int i = 0; i < 2; i++) {
            int id = tid + i * 256;
            int wr = id >> 5, wc = (id & 31) << 2;
            cp16(&u.p.w[0][wr * 136 + wc], &Wg[(size_t)wr * DIM + wc], 16);
        }
        CP_COMMIT();

        float c[4][4];
#pragma unroll
        for (int i = 0; i < 4; i++) { c[i][0] = c[i][1] = c[i][2] = c[i][3] = 0.f; }

        for (int kk = 0; kk < 8; kk++) {
            int b = kk & 1;
            if (kk < 7) {
                int krel = (kk + 1) * 16;
                if (stagerA)
                    cp16(&u.p.a[b ^ 1][r * 20 + c4], &x[(size_t)gr * DIM + krel + c4],
                         gr < n ? 16 : 0);
#pragma unroll
                for (int i = 0; i < 2; i++) {
                    int id = tid + i * 256;
                    int wr = id >> 5, wc = (id & 31) << 2;
                    cp16(&u.p.w[b ^ 1][wr * 136 + wc], &Wg[(size_t)(krel + wr) * DIM + wc], 16);
                }
                CP_COMMIT();
                CP_WAIT_1();
            } else {
                CP_WAIT_0();
            }
            __syncthreads();
            // x-part interleaved hx16 store for this chunk's columns
            if (stagerA && gr < n) {
                float4 v = *(float4*)&u.p.a[b][r * 20 + c4];
                __half2 p0 = __floats2half2_rn(v.x, v.y);
                __half2 p1 = __floats2half2_rn(v.z, v.w);
                uint2 q; q.x = *(unsigned*)&p0; q.y = *(unsigned*)&p1;
                int laneCol = kk * 4 + (tid & 3);
                *(uint2*)&d_hx16[(size_t)gr * 256 + laneCol * 8 + 4] = q;
            }
            {
                const float* A = u.p.a[b];
                const float* W = u.p.w[b];
#pragma unroll
                for (int k8 = 0; k8 < 16; k8 += 8) {
                    unsigned a0 = __float_as_uint(A[(warpM * 16 + g) * 20 + k8 + tig]);
                    unsigned a1 = __float_as_uint(A[(warpM * 16 + g + 8) * 20 + k8 + tig]);
                    unsigned a2 = __float_as_uint(A[(warpM * 16 + g) * 20 + k8 + tig + 4]);
                    unsigned a3 = __float_as_uint(A[(warpM * 16 + g + 8) * 20 + k8 + tig + 4]);
#pragma unroll
                    for (int n8 = 0; n8 < 4; n8++) {
                        int cb = warpN * 32 + n8 * 8 + g;
                        unsigned b0 = __float_as_uint(W[(k8 + tig) * 136 + cb]);
                        unsigned b1 = __float_as_uint(W[(k8 + tig + 4) * 136 + cb]);
                        mma_tf32(c[n8], a0, a1, a2, a3, b0, b1);
                    }
                }
            }
            __syncthreads();
        }
        // dump frags -> ot [32][132]
        {
            int rb = warpM * 16, cb = warpN * 32;
#pragma unroll
            for (int n8 = 0; n8 < 4; n8++) {
                int cc = cb + n8 * 8 + 2 * tig;
                u.ot[(rb + g) * 132 + cc] = c[n8][0];
                u.ot[(rb + g) * 132 + cc + 1] = c[n8][1];
                u.ot[(rb + g + 8) * 132 + cc] = c[n8][2];
                u.ot[(rb + g + 8) * 132 + cc + 1] = c[n8][3];
            }
        }
        __syncthreads();
        // h-part store + attention logits: 8 warps x 4 rows
        int tx = lane, ty = wid;
        float4 as4 = *(const float4*)&att_src[tx << 2];
        float4 ad4 = *(const float4*)&att_dst[tx << 2];
#pragma unroll
        for (int r4 = 0; r4 < 4; r4++) {
            int row = ty * 4 + r4;
            int grr = rowBase + row;
            float4 hv = *(float4*)&u.ot[row * 132 + (tx << 2)];
            if (grr < n) {
                __half2 p0 = __floats2half2_rn(hv.x, hv.y);
                __half2 p1 = __floats2half2_rn(hv.z, hv.w);
                uint2 q; q.x = *(unsigned*)&p0; q.y = *(unsigned*)&p1;
                *(uint2*)&d_hx16[(size_t)grr * 256 + tx * 8] = q;
            }
            float ps = hv.x * as4.x + hv.y * as4.y + hv.z * as4.z + hv.w * as4.w;
            float pd = hv.x * ad4.x + hv.y * ad4.y + hv.z * ad4.z + hv.w * ad4.w;
#pragma unroll
            for (int o = 4; o; o >>= 1) {
                ps += __shfl_xor_sync(0xffffffffu, ps, o);
                pd += __shfl_xor_sync(0xffffffffu, pd, o);
            }
            if ((tx & 7) == 0 && grr < n) {
                int hd = tx >> 3;
                d_asrc[grr * 4 + hd] = ps;
                d_adst[grr * 4 + hd] = pd;
            }
        }
    } else {
        // ---------------- prep branch: B = Wl@Wp2, C = Wr@Wp2 + I, dvec ---------------
        int pbid = bid - nbS - nbG;
        const float* Wp2 = Wp + DIM * DIM;
        if (pbid == 4) {
            int nn = tid;
            if (nn < DIM) {
                float sacc = bp[nn];
                for (int j = 0; j < DIM; j++) sacc += bl[j] * Wp2[j * DIM + nn];
                d_dvec[nn] = sacc;
            }
            return;
        }
        float* xs = u.pr.xs;   // [64][16]
        float* ws = u.pr.ws;   // [16][128]
        int tx = lane, ty = wid;
        int rowBase = pbid * 64;
        const float* A = (rowBase < 128) ? Wl : Wr;
        int aBase = (rowBase < 128) ? rowBase : rowBase - 128;
        float acc[8][4];
#pragma unroll
        for (int rr = 0; rr < 8; rr++) { acc[rr][0] = acc[rr][1] = acc[rr][2] = acc[rr][3] = 0.f; }
        for (int kk = 0; kk < 8; kk++) {
            int r = tid >> 2, k4 = (tid & 3) << 2;
            *(float4*)&xs[r * 16 + k4] =
                *(const float4*)&A[(size_t)(aBase + r) * DIM + kk * 16 + k4];
#pragma unroll
            for (int i = 0; i < 2; i++) {
                int id = tid + i * 256;
                int wr = id >> 5, wc = (id & 31) << 2;
                *(float4*)&ws[wr * 128 + wc] =
                    *(const float4*)&Wp2[(size_t)(kk * 16 + wr) * DIM + wc];
            }
            __syncthreads();
#pragma unroll
            for (int k = 0; k < 16; k++) {
                float4 b = *(float4*)&ws[k * 128 + (tx << 2)];
#pragma unroll
                for (int r8 = 0; r8 < 8; r8++) {
                    float a = xs[(ty * 8 + r8) * 16 + k];
                    acc[r8][0] += a * b.x; acc[r8][1] += a * b.y;
                    acc[r8][2] += a * b.z; acc[r8][3] += a * b.w;
                }
            }
            __syncthreads();
        }
#pragma unroll
        for (int r8 = 0; r8 < 8; r8++) {
            int vr = rowBase + ty * 8 + r8;
            int col = tx << 2;
            if (vr < 128) {
                *(float4*)&d_B[vr * DIM + col] =
                    make_float4(acc[r8][0], acc[r8][1], acc[r8][2], acc[r8][3]);
            } else {
                int rr = vr - 128;
                float4 v = make_float4(acc[r8][0], acc[r8][1], acc[r8][2], acc[r8][3]);
                if (rr >= col && rr < col + 4) {
                    if (rr == col) v.x += 1.f;
                    else if (rr == col + 1) v.y += 1.f;
                    else if (rr == col + 2) v.z += 1.f;
                    else v.w += 1.f;
                }
                *(float4*)&d_C[rr * DIM + col] = v;
            }
        }
    }
}

// ---- gather: warp per dst node (round-7 proven version, untouched) ----
__global__ __launch_bounds__(256) void k_gather(const float* __restrict__ b_gat, int n) {
    __shared__ float s_ex[8][32][4];
    int tid = threadIdx.x, lane = tid & 31, wb = tid >> 5;
    int w = (blockIdx.x * blockDim.x + tid) >> 5;
    if (w >= n) return;
    int hd = lane >> 3;
    int c = lane << 2;
    int fill = d_fill[w];
    int deg = fill < BCAP ? fill : BCAP;
    float4 ad4 = *(const float4*)&d_adst[w * 4];
    float4 g = make_float4(0.f, 0.f, 0.f, 0.f);
    float4 sa = make_float4(0.f, 0.f, 0.f, 0.f);
    float den = 0.f;
    const uint4* hx = (const uint4*)d_hx16;

    for (int base = 0; base < deg; base += 32) {
        int cnt = deg - base; if (cnt > 32) cnt = 32;
        int myS = 0;
        float4 ex4 = make_float4(0.f, 0.f, 0.f, 0.f);
        if (lane < cnt) {
            myS = d_esrc[w * BCAP + base + lane];
            float4 as = *(const float4*)&d_asrc[myS * 4];
            float e0 = as.x + ad4.x, e1 = as.y + ad4.y;
            float e2 = as.z + ad4.z, e3 = as.w + ad4.w;
            e0 = e0 > 0.f ? e0 : 0.2f * e0;
            e1 = e1 > 0.f ? e1 : 0.2f * e1;
            e2 = e2 > 0.f ? e2 : 0.2f * e2;
            e3 = e3 > 0.f ? e3 : 0.2f * e3;
            ex4 = make_float4(__expf(e0), __expf(e1), __expf(e2), __expf(e3));
        }
        *(float4*)&s_ex[wb][lane][0] = ex4;
        __syncwarp();
#pragma unroll 8
        for (int j = 0; j < cnt; j++) {
            int s = __shfl_sync(0xffffffffu, myS, j);
            float ex = s_ex[wb][j][hd];
            den += ex;
            uint4 q = __ldg(&hx[(size_t)s * 32 + lane]);
            float2 h01 = __half22float2(*(__half2*)&q.x);
            float2 h23 = __half22float2(*(__half2*)&q.y);
            float2 x01 = __half22float2(*(__half2*)&q.z);
            float2 x23 = __half22float2(*(__half2*)&q.w);
            g.x += h01.x * ex; g.y += h01.y * ex; g.z += h23.x * ex; g.w += h23.y * ex;
            sa.x += x01.x; sa.y += x01.y; sa.z += x23.x; sa.w += x23.y;
        }
        __syncwarp();
    }

    int oc = d_ovf_cnt;
    if (oc > 0) {
        if (oc > OVF_CAP) oc = OVF_CAP;
        for (int k = 0; k < oc; k++) {
            if (d_ovf[2 * k + 1] == w) {
                int s = d_ovf[2 * k];
                float asr = __ldg(&d_asrc[s * 4 + hd]);
                float adst = (hd == 0) ? ad4.x : (hd == 1) ? ad4.y : (hd == 2) ? ad4.z : ad4.w;
                float ee = asr + adst;
                ee = ee > 0.f ? ee : 0.2f * ee;
                float ex = __expf(ee);
                den += ex;
                uint4 q = __ldg(&hx[(size_t)s * 32 + lane]);
                float2 h01 = __half22float2(*(__half2*)&q.x);
                float2 h23 = __half22float2(*(__half2*)&q.y);
                float2 x01 = __half22float2(*(__half2*)&q.z);
                float2 x23 = __half22float2(*(__half2*)&q.w);
                g.x += h01.x * ex; g.y += h01.y * ex; g.z += h23.x * ex; g.w += h23.y * ex;
                sa.x += x01.x; sa.y += x01.y; sa.z += x23.x; sa.w += x23.y;
            }
        }
    }

    // self-loop (GAT only)
    {
        float asr = d_asrc[w * 4 + hd];
        float adst = (hd == 0) ? ad4.x : (hd == 1) ? ad4.y : (hd == 2) ? ad4.z : ad4.w;
        float ee = asr + adst;
        ee = ee > 0.f ? ee : 0.2f * ee;
        float exs = __expf(ee);
        den += exs;
        uint4 q = __ldg(&hx[(size_t)w * 32 + lane]);
        float2 h01 = __half22float2(*(__half2*)&q.x);
        float2 h23 = __half22float2(*(__half2*)&q.y);
        g.x += h01.x * exs; g.y += h01.y * exs; g.z += h23.x * exs; g.w += h23.y * exs;
    }

    float inv = 1.f / (den + 1e-16f);
    float4 bg = *(const float4*)&b_gat[c];
    size_t off = (size_t)w * DIM + c;
    *(float4*)&d_gacc[off] = make_float4(g.x * inv + bg.x, g.y * inv + bg.y,
                                         g.z * inv + bg.z, g.w * inv + bg.w);
    float dg = fill > 0 ? (float)fill : 1.f;
    float idg = 1.f / dg;
    *(float4*)&d_sacc[off] = make_float4(sa.x * idg, sa.y * idg, sa.z * idg, sa.w * idg);
}

// ---- final fused 3-GEMM (K=384, chunk=32, double-buffered) + LN + re-zero ----
__global__ void k_final(const float* __restrict__ x, const float* __restrict__ Wp,
                        const float* __restrict__ gamma, const float* __restrict__ beta,
                        float* __restrict__ out, int n) {
    extern __shared__ float dsm[];
    float* sa = dsm;                    // [2][64*36]
    float* sw = dsm + 2 * 64 * 36;      // [2][32*136]
    float* ot = dsm;                    // epilogue overlay [64*132]
    int tid = threadIdx.x, lane = tid & 31, wid = tid >> 5;
    int rowBase = blockIdx.x * 64;

    // re-zero scratch for the next replay
    if (tid < 64) {
        int zi = rowBase + tid;
        if (zi < n) d_fill[zi] = 0;
    }
    if (blockIdx.x == 0 && tid == 64) d_ovf_cnt = 0;

    int warpM = wid & 3, warpN = wid >> 2;
    int g = lane >> 2, tig = lane & 3;

    float c[8][4];
#pragma unroll
    for (int i = 0; i < 8; i++) { c[i][0] = c[i][1] = c[i][2] = c[i][3] = 0.f; }

    auto stage = [&](int j, int buf) {
        int seg = j >> 2;
        int krel = (j & 3) * 32;
        const float* src = (seg == 0) ? d_gacc : (seg == 1) ? d_sacc : x;
        const float* wseg = (seg == 0) ? Wp : (seg == 1) ? d_B : d_C;
#pragma unroll
        for (int i = 0; i < 2; i++) {
            int id = tid + i * 256;
            int r = id >> 3, c4 = (id & 7) << 2;
            int gr = rowBase + r;
            cp16(&sa[buf * 2304 + r * 36 + c4], &src[(size_t)gr * DIM + krel + c4],
                 gr < n ? 16 : 0);
        }
#pragma unroll
        for (int i = 0; i < 4; i++) {
            int id = tid + i * 256;
            int wr = id >> 5, wc = (id & 31) << 2;
            cp16(&sw[buf * 4352 + wr * 136 + wc], &wseg[(size_t)(krel + wr) * DIM + wc], 16);
        }
        CP_COMMIT();
    };

    stage(0, 0);

    for (int kk = 0; kk < 12; kk++) {
        int b = kk & 1;
        if (kk < 11) {
            stage(kk + 1, b ^ 1);
            CP_WAIT_1();
        } else {
            CP_WAIT_0();
        }
        __syncthreads();
        const float* A = &sa[b * 2304];
        const float* W = &sw[b * 4352];
#pragma unroll
        for (int k8 = 0; k8 < 32; k8 += 8) {
            unsigned a0 = __float_as_uint(A[(warpM * 16 + g) * 36 + k8 + tig]);
            unsigned a1 = __float_as_uint(A[(warpM * 16 + g + 8) * 36 + k8 + tig]);
            unsigned a2 = __float_as_uint(A[(warpM * 16 + g) * 36 + k8 + tig + 4]);
            unsigned a3 = __float_as_uint(A[(warpM * 16 + g + 8) * 36 + k8 + tig + 4]);
#pragma unroll
            for (int n8 = 0; n8 < 8; n8++) {
                int cb = warpN * 64 + n8 * 8 + g;
                unsigned b0 = __float_as_uint(W[(k8 + tig) * 136 + cb]);
                unsigned b1 = __float_as_uint(W[(k8 + tig + 4) * 136 + cb]);
                mma_tf32(c[n8], a0, a1, a2, a3, b0, b1);
            }
        }
        __syncthreads();
    }
    {
        int rb = warpM * 16, cb = warpN * 64;
#pragma unroll
        for (int n8 = 0; n8 < 8; n8++) {
            int cq = cb + n8 * 8 + 2 * tig;
            ot[(rb + g) * 132 + cq] = c[n8][0];     ot[(rb + g) * 132 + cq + 1] = c[n8][1];
            ot[(rb + g + 8) * 132 + cq] = c[n8][2]; ot[(rb + g + 8) * 132 + cq + 1] = c[n8][3];
        }
    }
    __syncthreads();
    int tx = lane, ty = wid;
    float4 dv = *(const float4*)&d_dvec[tx << 2];
    float4 gm = *(const float4*)&gamma[tx << 2];
    float4 bt = *(const float4*)&beta[tx << 2];
#pragma unroll
    for (int r8 = 0; r8 < 8; r8++) {
        float4 av = *(float4*)&ot[(ty * 8 + r8) * 132 + (tx << 2)];
        float v0 = av.x + dv.x, v1 = av.y + dv.y;
        float v2 = av.z + dv.z, v3 = av.w + dv.w;
        float sum = v0 + v1 + v2 + v3;
        float sq = v0 * v0 + v1 * v1 + v2 * v2 + v3 * v3;
#pragma unroll
        for (int o = 16; o; o >>= 1) {
            sum += __shfl_xor_sync(0xffffffffu, sum, o);
            sq  += __shfl_xor_sync(0xffffffffu, sq, o);
        }
        float mu = sum * (1.f / 128.f);
        float var = sq * (1.f / 128.f) - mu * mu;
        float rstd = rsqrtf(var + 1e-5f);
        int grr = rowBase + ty * 8 + r8;
        if (grr < n) {
            float4 o4;
            o4.x = (v0 - mu) * rstd * gm.x + bt.x;
            o4.y = (v1 - mu) * rstd * gm.y + bt.y;
            o4.z = (v2 - mu) * rstd * gm.z + bt.z;
            o4.w = (v3 - mu) * rstd * gm.w + bt.w;
            *(float4*)&out[(size_t)grr * DIM + (tx << 2)] = o4;
        }
    }
}

extern "C" void kernel_launch(void* const* d_in, const int* in_sizes, int n_in,
                              void* d_out, int out_size) {
    const float* x       = (const float*)d_in[0];
    const void*  eidx    = d_in[1];
    const float* W_gat   = (const float*)d_in[2];
    const float* att_src = (const float*)d_in[3];
    const float* att_dst = (const float*)d_in[4];
    const float* b_gat   = (const float*)d_in[5];
    const float* W_l     = (const float*)d_in[6];
    const float* b_l     = (const float*)d_in[7];
    const float* W_r     = (const float*)d_in[8];
    const float* W_proj  = (const float*)d_in[9];
    const float* b_proj  = (const float*)d_in[10];
    const float* gamma   = (const float*)d_in[11];
    const float* beta    = (const float*)d_in[12];

    int n = in_sizes[0] / DIM;
    int E = in_sizes[1] / 2;
    int nbG = (n + 31) / 32;
    int nbS = ((E + 3) / 4 + 255) / 256;

    const int SMEM_F = (2 * 64 * 36 + 2 * 32 * 136) * 4;   // 53,248 B
    cudaFuncSetAttribute(k_final, cudaFuncAttributeMaxDynamicSharedMemorySize, SMEM_F);

    k_fused<<<nbG + nbS + 5, 256>>>(x, W_gat, att_src, att_dst, (const int*)eidx,
                                    W_l, W_r, b_l, W_proj, b_proj, n, E, nbG, nbS); // 1
    k_gather<<<(n * 32 + 255) / 256, 256>>>(b_gat, n);                              // 2
    k_final<<<(n + 63) / 64, 256, SMEM_F>>>(x, W_proj, gamma, beta, (float*)d_out, n); // 3
}

// round 15
// speedup vs baseline: 1.5289x; 1.5289x over previous
#include <cuda_runtime.h>
#include <cuda_fp16.h>

#define DIM 128
#define HEADS 4
#define NMAX 50000
#define BCAP 64
#define OVF_CAP 2048

// ---- device scratch ----
__device__ __half d_hx16[NMAX * 256];    // per node, per lane c: [h(4 halves), x(4 halves)]
__device__ float d_asrc[NMAX * HEADS];
__device__ float d_adst[NMAX * HEADS];
__device__ float d_gacc[NMAX * DIM];     // gat_out (incl b_gat)
__device__ float d_sacc[NMAX * DIM];     // SAGE mean
__device__ float d_B[DIM * DIM];         // W_sage_l @ Wp2
__device__ float d_C[DIM * DIM];         // W_sage_r @ Wp2 + I
__device__ float d_dvec[DIM];            // b_sage_l @ Wp2 + b_proj
__device__ int   d_fill[NMAX];           // zero at module load; re-zeroed by k_final tail
__device__ int   d_esrc[NMAX * BCAP];
__device__ int   d_ovf[OVF_CAP * 2];
__device__ int   d_ovf_cnt;              // zero at module load; re-zeroed by k_final tail

__device__ __forceinline__ void mma_tf32(float c[4], unsigned a0, unsigned a1,
                                         unsigned a2, unsigned a3,
                                         unsigned b0, unsigned b1) {
    asm volatile(
        "mma.sync.aligned.m16n8k8.row.col.f32.tf32.tf32.f32 "
        "{%0,%1,%2,%3}, {%4,%5,%6,%7}, {%8,%9}, {%0,%1,%2,%3};"
        : "+f"(c[0]), "+f"(c[1]), "+f"(c[2]), "+f"(c[3])
        : "r"(a0), "r"(a1), "r"(a2), "r"(a3), "r"(b0), "r"(b1));
}

__device__ __forceinline__ void cp16(void* sptr, const void* g, int srcsize) {
    unsigned sm = (unsigned)__cvta_generic_to_shared(sptr);
    asm volatile("cp.async.cg.shared.global [%0], [%1], 16, %2;"
                 :: "r"(sm), "l"(g), "r"(srcsize));
}
#define CP_COMMIT() asm volatile("cp.async.commit_group;")
#define CP_WAIT_1() asm volatile("cp.async.wait_group 1;")
#define CP_WAIT_0() asm volatile("cp.async.wait_group 0;")

__device__ __forceinline__ void mma_chunk64(const float* A, const float* W, float c[8][4],
                                            int warpM, int warpN, int g, int tig) {
#pragma unroll
    for (int k8 = 0; k8 < 16; k8 += 8) {
        unsigned a0 = __float_as_uint(A[(warpM * 16 + g) * 20 + k8 + tig]);
        unsigned a1 = __float_as_uint(A[(warpM * 16 + g + 8) * 20 + k8 + tig]);
        unsigned a2 = __float_as_uint(A[(warpM * 16 + g) * 20 + k8 + tig + 4]);
        unsigned a3 = __float_as_uint(A[(warpM * 16 + g + 8) * 20 + k8 + tig + 4]);
#pragma unroll
        for (int n8 = 0; n8 < 8; n8++) {
            int cb = warpN * 64 + n8 * 8 + g;
            unsigned b0 = __float_as_uint(W[(k8 + tig) * 136 + cb]);
            unsigned b1 = __float_as_uint(W[(k8 + tig + 4) * 136 + cb]);
            mma_tf32(c[n8], a0, a1, a2, a3, b0, b1);
        }
    }
}

struct PipeSmem { float a[2][64 * 20]; float w[2][16 * 136]; };
union KSm {
    PipeSmem p;
    float ot[64 * 132];
    struct { float xs[64 * 16]; float ws[16 * 128]; } pr;
    int is64;
};

// ===== fused kernel: scatter blocks FIRST, then gemm_h blocks, then prep blocks =====
// launch_bounds(256, 4): cap regs at 64 so the scatter branch gets 4 CTAs/SM residency.
__global__ __launch_bounds__(256, 4)
void k_fused(const float* __restrict__ x, const float* __restrict__ Wg,
             const float* __restrict__ att_src, const float* __restrict__ att_dst,
             const int* __restrict__ eidx,
             const float* __restrict__ Wl, const float* __restrict__ Wr,
             const float* __restrict__ bl, const float* __restrict__ Wp,
             const float* __restrict__ bp,
             int n, int E, int nbG, int nbS) {
    __shared__ KSm u;
    int bid = blockIdx.x;
    int tid = threadIdx.x, lane = tid & 31, wid = tid >> 5;

    if (bid < nbS) {
        // ---------------- scatter branch: 4 edges per thread --------------------------
        const unsigned* eraw = (const unsigned*)eidx;
        if (tid < 32) {
            unsigned v = eraw[2 * tid + 1];
            unsigned ball = __ballot_sync(0xffffffffu, v == 0u);
            if (tid == 0) u.is64 = (ball == 0xffffffffu) ? 1 : 0;
        }
        __syncthreads();
        int is64 = u.is64;
        int t = bid * 256 + tid;
        int base = t * 4;
        if (base >= E) return;
        int m = E - base; if (m > 4) m = 4;
        int s[4], d[4];
        if (is64) {
            const long long* p = (const long long*)eidx;
#pragma unroll
            for (int j = 0; j < 4; j++) if (j < m) {
                s[j] = (int)__ldg(&p[base + j]); d[j] = (int)__ldg(&p[E + base + j]);
            }
        } else {
#pragma unroll
            for (int j = 0; j < 4; j++) if (j < m) {
                s[j] = __ldg(&eidx[base + j]); d[j] = __ldg(&eidx[E + base + j]);
            }
        }
#pragma unroll
        for (int j = 0; j < 4; j++) if (j < m) {
            int slot = atomicAdd(&d_fill[d[j]], 1);
            if (slot < BCAP) {
                d_esrc[d[j] * BCAP + slot] = s[j];
            } else {
                int o = atomicAdd(&d_ovf_cnt, 1);
                if (o < OVF_CAP) { d_ovf[2 * o] = s[j]; d_ovf[2 * o + 1] = d[j]; }
            }
        }
    } else if (bid < nbS + nbG) {
        // ---------------- GEMM1 branch: h = x @ W_gat + logits + hx16 stores ----------
        int rowBase = (bid - nbS) * 64;
        int warpM = wid & 3, warpN = wid >> 2;
        int g = lane >> 2, tig = lane & 3;
        int r = tid >> 2, c4 = (tid & 3) << 2;
        int gr = rowBase + r;

        cp16(&u.p.a[0][r * 20 + c4], &x[(size_t)gr * DIM + c4], gr < n ? 16 : 0);
#pragma unroll
        for (int i = 0; i < 2; i++) {
            int id = tid + i * 256;
            int wr = id >> 5, wc = (id & 31) << 2;
            cp16(&u.p.w[0][wr * 136 + wc], &Wg[(size_t)wr * DIM + wc], 16);
        }
        CP_COMMIT();

        float c[8][4];
#pragma unroll
        for (int i = 0; i < 8; i++) { c[i][0] = c[i][1] = c[i][2] = c[i][3] = 0.f; }

        for (int kk = 0; kk < 8; kk++) {
            int b = kk & 1;
            if (kk < 7) {
                int krel = (kk + 1) * 16;
                cp16(&u.p.a[b ^ 1][r * 20 + c4], &x[(size_t)gr * DIM + krel + c4],
                     gr < n ? 16 : 0);
#pragma unroll
                for (int i = 0; i < 2; i++) {
                    int id = tid + i * 256;
                    int wr = id >> 5, wc = (id & 31) << 2;
                    cp16(&u.p.w[b ^ 1][wr * 136 + wc], &Wg[(size_t)(krel + wr) * DIM + wc], 16);
                }
                CP_COMMIT();
                CP_WAIT_1();
            } else {
                CP_WAIT_0();
            }
            __syncthreads();
            if (gr < n) {
                float4 v = *(float4*)&u.p.a[b][r * 20 + c4];
                __half2 p0 = __floats2half2_rn(v.x, v.y);
                __half2 p1 = __floats2half2_rn(v.z, v.w);
                uint2 q; q.x = *(unsigned*)&p0; q.y = *(unsigned*)&p1;
                int laneCol = kk * 4 + (tid & 3);
                *(uint2*)&d_hx16[(size_t)gr * 256 + laneCol * 8 + 4] = q;
            }
            mma_chunk64(u.p.a[b], u.p.w[b], c, warpM, warpN, g, tig);
            __syncthreads();
        }
        {
            int rb = warpM * 16, cb = warpN * 64;
#pragma unroll
            for (int n8 = 0; n8 < 8; n8++) {
                int cc = cb + n8 * 8 + 2 * tig;
                u.ot[(rb + g) * 132 + cc] = c[n8][0];
                u.ot[(rb + g) * 132 + cc + 1] = c[n8][1];
                u.ot[(rb + g + 8) * 132 + cc] = c[n8][2];
                u.ot[(rb + g + 8) * 132 + cc + 1] = c[n8][3];
            }
        }
        __syncthreads();
        int tx = lane, ty = wid;
        float4 as4 = *(const float4*)&att_src[tx << 2];
        float4 ad4 = *(const float4*)&att_dst[tx << 2];
#pragma unroll
        for (int r8 = 0; r8 < 8; r8++) {
            int grr = rowBase + ty * 8 + r8;
            float4 hv = *(float4*)&u.ot[(ty * 8 + r8) * 132 + (tx << 2)];
            if (grr < n) {
                __half2 p0 = __floats2half2_rn(hv.x, hv.y);
                __half2 p1 = __floats2half2_rn(hv.z, hv.w);
                uint2 q; q.x = *(unsigned*)&p0; q.y = *(unsigned*)&p1;
                *(uint2*)&d_hx16[(size_t)grr * 256 + tx * 8] = q;
            }
            float ps = hv.x * as4.x + hv.y * as4.y + hv.z * as4.z + hv.w * as4.w;
            float pd = hv.x * ad4.x + hv.y * ad4.y + hv.z * ad4.z + hv.w * ad4.w;
#pragma unroll
            for (int o = 4; o; o >>= 1) {
                ps += __shfl_xor_sync(0xffffffffu, ps, o);
                pd += __shfl_xor_sync(0xffffffffu, pd, o);
            }
            if ((tx & 7) == 0 && grr < n) {
                int hd = tx >> 3;
                d_asrc[grr * 4 + hd] = ps;
                d_adst[grr * 4 + hd] = pd;
            }
        }
    } else {
        // ---------------- prep branch: B = Wl@Wp2, C = Wr@Wp2 + I, dvec ---------------
        int pbid = bid - nbS - nbG;
        const float* Wp2 = Wp + DIM * DIM;
        if (pbid == 4) {
            int nn = tid;
            if (nn < DIM) {
                float sacc = bp[nn];
                for (int j = 0; j < DIM; j++) sacc += bl[j] * Wp2[j * DIM + nn];
                d_dvec[nn] = sacc;
            }
            return;
        }
        float* xs = u.pr.xs;   // [64][16]
        float* ws = u.pr.ws;   // [16][128]
        int tx = lane, ty = wid;
        int rowBase = pbid * 64;
        const float* A = (rowBase < 128) ? Wl : Wr;
        int aBase = (rowBase < 128) ? rowBase : rowBase - 128;
        float acc[8][4];
#pragma unroll
        for (int rr = 0; rr < 8; rr++) { acc[rr][0] = acc[rr][1] = acc[rr][2] = acc[rr][3] = 0.f; }
        for (int kk = 0; kk < 8; kk++) {
            int r = tid >> 2, k4 = (tid & 3) << 2;
            *(float4*)&xs[r * 16 + k4] =
                *(const float4*)&A[(size_t)(aBase + r) * DIM + kk * 16 + k4];
#pragma unroll
            for (int i = 0; i < 2; i++) {
                int id = tid + i * 256;
                int wr = id >> 5, wc = (id & 31) << 2;
                *(float4*)&ws[wr * 128 + wc] =
                    *(const float4*)&Wp2[(size_t)(kk * 16 + wr) * DIM + wc];
            }
            __syncthreads();
#pragma unroll
            for (int k = 0; k < 16; k++) {
                float4 b = *(float4*)&ws[k * 128 + (tx << 2)];
#pragma unroll
                for (int r8 = 0; r8 < 8; r8++) {
                    float a = xs[(ty * 8 + r8) * 16 + k];
                    acc[r8][0] += a * b.x; acc[r8][1] += a * b.y;
                    acc[r8][2] += a * b.z; acc[r8][3] += a * b.w;
                }
            }
            __syncthreads();
        }
#pragma unroll
        for (int r8 = 0; r8 < 8; r8++) {
            int vr = rowBase + ty * 8 + r8;
            int col = tx << 2;
            if (vr < 128) {
                *(float4*)&d_B[vr * DIM + col] =
                    make_float4(acc[r8][0], acc[r8][1], acc[r8][2], acc[r8][3]);
            } else {
                int rr = vr - 128;
                float4 v = make_float4(acc[r8][0], acc[r8][1], acc[r8][2], acc[r8][3]);
                if (rr >= col && rr < col + 4) {
                    if (rr == col) v.x += 1.f;
                    else if (rr == col + 1) v.y += 1.f;
                    else if (rr == col + 2) v.z += 1.f;
                    else v.w += 1.f;
                }
                *(float4*)&d_C[rr * DIM + col] = v;
            }
        }
    }
}

// ---- gather: warp per dst node (round-7 proven version, untouched) ----
__global__ __launch_bounds__(256) void k_gather(const float* __restrict__ b_gat, int n) {
    __shared__ float s_ex[8][32][4];
    int tid = threadIdx.x, lane = tid & 31, wb = tid >> 5;
    int w = (blockIdx.x * blockDim.x + tid) >> 5;
    if (w >= n) return;
    int hd = lane >> 3;
    int c = lane << 2;
    int fill = d_fill[w];
    int deg = fill < BCAP ? fill : BCAP;
    float4 ad4 = *(const float4*)&d_adst[w * 4];
    float4 g = make_float4(0.f, 0.f, 0.f, 0.f);
    float4 sa = make_float4(0.f, 0.f, 0.f, 0.f);
    float den = 0.f;
    const uint4* hx = (const uint4*)d_hx16;

    for (int base = 0; base < deg; base += 32) {
        int cnt = deg - base; if (cnt > 32) cnt = 32;
        int myS = 0;
        float4 ex4 = make_float4(0.f, 0.f, 0.f, 0.f);
        if (lane < cnt) {
            myS = d_esrc[w * BCAP + base + lane];
            float4 as = *(const float4*)&d_asrc[myS * 4];
            float e0 = as.x + ad4.x, e1 = as.y + ad4.y;
            float e2 = as.z + ad4.z, e3 = as.w + ad4.w;
            e0 = e0 > 0.f ? e0 : 0.2f * e0;
            e1 = e1 > 0.f ? e1 : 0.2f * e1;
            e2 = e2 > 0.f ? e2 : 0.2f * e2;
            e3 = e3 > 0.f ? e3 : 0.2f * e3;
            ex4 = make_float4(__expf(e0), __expf(e1), __expf(e2), __expf(e3));
        }
        *(float4*)&s_ex[wb][lane][0] = ex4;
        __syncwarp();
#pragma unroll 8
        for (int j = 0; j < cnt; j++) {
            int s = __shfl_sync(0xffffffffu, myS, j);
            float ex = s_ex[wb][j][hd];
            den += ex;
            uint4 q = __ldg(&hx[(size_t)s * 32 + lane]);
            float2 h01 = __half22float2(*(__half2*)&q.x);
            float2 h23 = __half22float2(*(__half2*)&q.y);
            float2 x01 = __half22float2(*(__half2*)&q.z);
            float2 x23 = __half22float2(*(__half2*)&q.w);
            g.x += h01.x * ex; g.y += h01.y * ex; g.z += h23.x * ex; g.w += h23.y * ex;
            sa.x += x01.x; sa.y += x01.y; sa.z += x23.x; sa.w += x23.y;
        }
        __syncwarp();
    }

    int oc = d_ovf_cnt;
    if (oc > 0) {
        if (oc > OVF_CAP) oc = OVF_CAP;
        for (int k = 0; k < oc; k++) {
            if (d_ovf[2 * k + 1] == w) {
                int s = d_ovf[2 * k];
                float asr = __ldg(&d_asrc[s * 4 + hd]);
                float adst = (hd == 0) ? ad4.x : (hd == 1) ? ad4.y : (hd == 2) ? ad4.z : ad4.w;
                float ee = asr + adst;
                ee = ee > 0.f ? ee : 0.2f * ee;
                float ex = __expf(ee);
                den += ex;
                uint4 q = __ldg(&hx[(size_t)s * 32 + lane]);
                float2 h01 = __half22float2(*(__half2*)&q.x);
                float2 h23 = __half22float2(*(__half2*)&q.y);
                float2 x01 = __half22float2(*(__half2*)&q.z);
                float2 x23 = __half22float2(*(__half2*)&q.w);
                g.x += h01.x * ex; g.y += h01.y * ex; g.z += h23.x * ex; g.w += h23.y * ex;
                sa.x += x01.x; sa.y += x01.y; sa.z += x23.x; sa.w += x23.y;
            }
        }
    }

    // self-loop (GAT only)
    {
        float asr = d_asrc[w * 4 + hd];
        float adst = (hd == 0) ? ad4.x : (hd == 1) ? ad4.y : (hd == 2) ? ad4.z : ad4.w;
        float ee = asr + adst;
        ee = ee > 0.f ? ee : 0.2f * ee;
        float exs = __expf(ee);
        den += exs;
        uint4 q = __ldg(&hx[(size_t)w * 32 + lane]);
        float2 h01 = __half22float2(*(__half2*)&q.x);
        float2 h23 = __half22float2(*(__half2*)&q.y);
        g.x += h01.x * exs; g.y += h01.y * exs; g.z += h23.x * exs; g.w += h23.y * exs;
    }

    float inv = 1.f / (den + 1e-16f);
    float4 bg = *(const float4*)&b_gat[c];
    size_t off = (size_t)w * DIM + c;
    *(float4*)&d_gacc[off] = make_float4(g.x * inv + bg.x, g.y * inv + bg.y,
                                         g.z * inv + bg.z, g.w * inv + bg.w);
    float dg = fill > 0 ? (float)fill : 1.f;
    float idg = 1.f / dg;
    *(float4*)&d_sacc[off] = make_float4(sa.x * idg, sa.y * idg, sa.z * idg, sa.w * idg);
}

// ---- final fused 3-GEMM (K=384, chunk=32, double-buffered) + LN + re-zero ----
__global__ void k_final(const float* __restrict__ x, const float* __restrict__ Wp,
                        const float* __restrict__ gamma, const float* __restrict__ beta,
                        float* __restrict__ out, int n) {
    extern __shared__ float dsm[];
    float* sa = dsm;                    // [2][64*36]
    float* sw = dsm + 2 * 64 * 36;      // [2][32*136]
    float* ot = dsm;                    // epilogue overlay [64*132]
    int tid = threadIdx.x, lane = tid & 31, wid = tid >> 5;
    int rowBase = blockIdx.x * 64;

    // re-zero scratch for the next replay
    if (tid < 64) {
        int zi = rowBase + tid;
        if (zi < n) d_fill[zi] = 0;
    }
    if (blockIdx.x == 0 && tid == 64) d_ovf_cnt = 0;

    int warpM = wid & 3, warpN = wid >> 2;
    int g = lane >> 2, tig = lane & 3;

    float c[8][4];
#pragma unroll
    for (int i = 0; i < 8; i++) { c[i][0] = c[i][1] = c[i][2] = c[i][3] = 0.f; }

    auto stage = [&](int j, int buf) {
        int seg = j >> 2;
        int krel = (j & 3) * 32;
        const float* src = (seg == 0) ? d_gacc : (seg == 1) ? d_sacc : x;
        const float* wseg = (seg == 0) ? Wp : (seg == 1) ? d_B : d_C;
#pragma unroll
        for (int i = 0; i < 2; i++) {
            int id = tid + i * 256;
            int r = id >> 3, c4 = (id & 7) << 2;
            int gr = rowBase + r;
            cp16(&sa[buf * 2304 + r * 36 + c4], &src[(size_t)gr * DIM + krel + c4],
                 gr < n ? 16 : 0);
        }
#pragma unroll
        for (int i = 0; i < 4; i++) {
            int id = tid + i * 256;
            int wr = id >> 5, wc = (id & 31) << 2;
            cp16(&sw[buf * 4352 + wr * 136 + wc], &wseg[(size_t)(krel + wr) * DIM + wc], 16);
        }
        CP_COMMIT();
    };

    stage(0, 0);

    for (int kk = 0; kk < 12; kk++) {
        int b = kk & 1;
        if (kk < 11) {
            stage(kk + 1, b ^ 1);
            CP_WAIT_1();
        } else {
            CP_WAIT_0();
        }
        __syncthreads();
        const float* A = &sa[b * 2304];
        const float* W = &sw[b * 4352];
#pragma unroll
        for (int k8 = 0; k8 < 32; k8 += 8) {
            unsigned a0 = __float_as_uint(A[(warpM * 16 + g) * 36 + k8 + tig]);
            unsigned a1 = __float_as_uint(A[(warpM * 16 + g + 8) * 36 + k8 + tig]);
            unsigned a2 = __float_as_uint(A[(warpM * 16 + g) * 36 + k8 + tig + 4]);
            unsigned a3 = __float_as_uint(A[(warpM * 16 + g + 8) * 36 + k8 + tig + 4]);
#pragma unroll
            for (int n8 = 0; n8 < 8; n8++) {
                int cb = warpN * 64 + n8 * 8 + g;
                unsigned b0 = __float_as_uint(W[(k8 + tig) * 136 + cb]);
                unsigned b1 = __float_as_uint(W[(k8 + tig + 4) * 136 + cb]);
                mma_tf32(c[n8], a0, a1, a2, a3, b0, b1);
            }
        }
        __syncthreads();
    }
    {
        int rb = warpM * 16, cb = warpN * 64;
#pragma unroll
        for (int n8 = 0; n8 < 8; n8++) {
            int cq = cb + n8 * 8 + 2 * tig;
            ot[(rb + g) * 132 + cq] = c[n8][0];     ot[(rb + g) * 132 + cq + 1] = c[n8][1];
            ot[(rb + g + 8) * 132 + cq] = c[n8][2]; ot[(rb + g + 8) * 132 + cq + 1] = c[n8][3];
        }
    }
    __syncthreads();
    int tx = lane, ty = wid;
    float4 dv = *(const float4*)&d_dvec[tx << 2];
    float4 gm = *(const float4*)&gamma[tx << 2];
    float4 bt = *(const float4*)&beta[tx << 2];
#pragma unroll
    for (int r8 = 0; r8 < 8; r8++) {
        float4 av = *(float4*)&ot[(ty * 8 + r8) * 132 + (tx << 2)];
        float v0 = av.x + dv.x, v1 = av.y + dv.y;
        float v2 = av.z + dv.z, v3 = av.w + dv.w;
        float sum = v0 + v1 + v2 + v3;
        float sq = v0 * v0 + v1 * v1 + v2 * v2 + v3 * v3;
#pragma unroll
        for (int o = 16; o; o >>= 1) {
            sum += __shfl_xor_sync(0xffffffffu, sum, o);
            sq  += __shfl_xor_sync(0xffffffffu, sq, o);
        }
        float mu = sum * (1.f / 128.f);
        float var = sq * (1.f / 128.f) - mu * mu;
        float rstd = rsqrtf(var + 1e-5f);
        int grr = rowBase + ty * 8 + r8;
        if (grr < n) {
            float4 o4;
            o4.x = (v0 - mu) * rstd * gm.x + bt.x;
            o4.y = (v1 - mu) * rstd * gm.y + bt.y;
            o4.z = (v2 - mu) * rstd * gm.z + bt.z;
            o4.w = (v3 - mu) * rstd * gm.w + bt.w;
            *(float4*)&out[(size_t)grr * DIM + (tx << 2)] = o4;
        }
    }
}

extern "C" void kernel_launch(void* const* d_in, const int* in_sizes, int n_in,
                              void* d_out, int out_size) {
    const float* x       = (const float*)d_in[0];
    const void*  eidx    = d_in[1];
    const float* W_gat   = (const float*)d_in[2];
    const float* att_src = (const float*)d_in[3];
    const float* att_dst = (const float*)d_in[4];
    const float* b_gat   = (const float*)d_in[5];
    const float* W_l     = (const float*)d_in[6];
    const float* b_l     = (const float*)d_in[7];
    const float* W_r     = (const float*)d_in[8];
    const float* W_proj  = (const float*)d_in[9];
    const float* b_proj  = (const float*)d_in[10];
    const float* gamma   = (const float*)d_in[11];
    const float* beta    = (const float*)d_in[12];

    int n = in_sizes[0] / DIM;
    int E = in_sizes[1] / 2;
    int nbG = (n + 63) / 64;
    int nbS = ((E + 3) / 4 + 255) / 256;

    const int SMEM_F = (2 * 64 * 36 + 2 * 32 * 136) * 4;   // 53,248 B
    cudaFuncSetAttribute(k_final, cudaFuncAttributeMaxDynamicSharedMemorySize, SMEM_F);

    k_fused<<<nbG + nbS + 5, 256>>>(x, W_gat, att_src, att_dst, (const int*)eidx,
                                    W_l, W_r, b_l, W_proj, b_proj, n, E, nbG, nbS); // 1
    k_gather<<<(n * 32 + 255) / 256, 256>>>(b_gat, n);                              // 2
    k_final<<<nbG, 256, SMEM_F>>>(x, W_proj, gamma, beta, (float*)d_out, n);        // 3
}

// round 16
// speedup vs baseline: 1.6182x; 1.0584x over previous
#include <cuda_runtime.h>
#include <cuda_fp16.h>

#define DIM 128
#define HEADS 4
#define NMAX 50000
#define BCAP 64
#define OVF_CAP 2048

// ---- device scratch ----
__device__ __half d_hx16[NMAX * 256];    // per node, per lane c: [h(4 halves), x(4 halves)]
__device__ float d_asrc[NMAX * HEADS];
__device__ float d_adst[NMAX * HEADS];
__device__ float d_gacc[NMAX * DIM];     // gat_out (incl b_gat)
__device__ float d_sacc[NMAX * DIM];     // SAGE mean
__device__ float d_B[DIM * DIM];         // W_sage_l @ Wp2
__device__ float d_C[DIM * DIM];         // W_sage_r @ Wp2 + I
__device__ float d_dvec[DIM];            // b_sage_l @ Wp2 + b_proj
__device__ int   d_fill[NMAX];           // zero at module load; re-zeroed by k_final tail
__device__ int   d_esrc[NMAX * BCAP];
__device__ int   d_ovf[OVF_CAP * 2];
__device__ int   d_ovf_cnt;              // zero at module load; re-zeroed by k_final tail

__device__ __forceinline__ void mma_tf32(float c[4], unsigned a0, unsigned a1,
                                         unsigned a2, unsigned a3,
                                         unsigned b0, unsigned b1) {
    asm volatile(
        "mma.sync.aligned.m16n8k8.row.col.f32.tf32.tf32.f32 "
        "{%0,%1,%2,%3}, {%4,%5,%6,%7}, {%8,%9}, {%0,%1,%2,%3};"
        : "+f"(c[0]), "+f"(c[1]), "+f"(c[2]), "+f"(c[3])
        : "r"(a0), "r"(a1), "r"(a2), "r"(a3), "r"(b0), "r"(b1));
}

__device__ __forceinline__ void cp16(void* sptr, const void* g, int srcsize) {
    unsigned sm = (unsigned)__cvta_generic_to_shared(sptr);
    asm volatile("cp.async.cg.shared.global [%0], [%1], 16, %2;"
                 :: "r"(sm), "l"(g), "r"(srcsize));
}
#define CP_COMMIT() asm volatile("cp.async.commit_group;")
#define CP_WAIT_1() asm volatile("cp.async.wait_group 1;")
#define CP_WAIT_0() asm volatile("cp.async.wait_group 0;")

__device__ __forceinline__ void mma_chunk64(const float* A, const float* W, float c[8][4],
                                            int warpM, int warpN, int g, int tig) {
#pragma unroll
    for (int k8 = 0; k8 < 16; k8 += 8) {
        unsigned a0 = __float_as_uint(A[(warpM * 16 + g) * 20 + k8 + tig]);
        unsigned a1 = __float_as_uint(A[(warpM * 16 + g + 8) * 20 + k8 + tig]);
        unsigned a2 = __float_as_uint(A[(warpM * 16 + g) * 20 + k8 + tig + 4]);
        unsigned a3 = __float_as_uint(A[(warpM * 16 + g + 8) * 20 + k8 + tig + 4]);
#pragma unroll
        for (int n8 = 0; n8 < 8; n8++) {
            int cb = warpN * 64 + n8 * 8 + g;
            unsigned b0 = __float_as_uint(W[(k8 + tig) * 136 + cb]);
            unsigned b1 = __float_as_uint(W[(k8 + tig + 4) * 136 + cb]);
            mma_tf32(c[n8], a0, a1, a2, a3, b0, b1);
        }
    }
}

struct PipeSmem { float a[2][64 * 20]; float w[2][16 * 136]; };
union KSm {
    PipeSmem p;
    float ot[64 * 132];
    struct { float xs[64 * 16]; float ws[16 * 128]; } pr;
    int is64;
};

// ===== fused kernel: prep blocks first, then INTERLEAVED scatter/gemm blocks =====
// launch_bounds(256, 4): cap regs at 64 so the scatter branch gets 4 CTAs/SM residency.
__global__ __launch_bounds__(256, 4)
void k_fused(const float* __restrict__ x, const float* __restrict__ Wg,
             const float* __restrict__ att_src, const float* __restrict__ att_dst,
             const int* __restrict__ eidx,
             const float* __restrict__ Wl, const float* __restrict__ Wr,
             const float* __restrict__ bl, const float* __restrict__ Wp,
             const float* __restrict__ bp,
             int n, int E, int nbG, int nbS) {
    __shared__ KSm u;
    int tid = threadIdx.x, lane = tid & 31, wid = tid >> 5;

    // ---- block -> branch mapping: 5 prep blocks first, then parity-interleaved ----
    int branch;        // 0 = scatter, 1 = gemm, 2 = prep
    int sub;           // index within branch
    {
        int bid = blockIdx.x;
        if (bid < 5) {
            branch = 2; sub = bid;
        } else {
            int t = bid - 5;
            int m2 = (nbS < nbG ? nbS : nbG) * 2;
            if (t < m2) {
                branch = t & 1;          // even -> scatter, odd -> gemm
                sub = t >> 1;
            } else {
                int r = t - m2;
                if (nbS > nbG) { branch = 0; sub = nbG + r; }
                else           { branch = 1; sub = nbS + r; }
            }
        }
    }

    if (branch == 0) {
        // ---------------- scatter branch: 4 edges per thread --------------------------
        const unsigned* eraw = (const unsigned*)eidx;
        if (tid < 32) {
            unsigned v = eraw[2 * tid + 1];
            unsigned ball = __ballot_sync(0xffffffffu, v == 0u);
            if (tid == 0) u.is64 = (ball == 0xffffffffu) ? 1 : 0;
        }
        __syncthreads();
        int is64 = u.is64;
        int t = sub * 256 + tid;
        int base = t * 4;
        if (base >= E) return;
        int m = E - base; if (m > 4) m = 4;
        int s[4], d[4];
        if (is64) {
            const long long* p = (const long long*)eidx;
#pragma unroll
            for (int j = 0; j < 4; j++) if (j < m) {
                s[j] = (int)__ldg(&p[base + j]); d[j] = (int)__ldg(&p[E + base + j]);
            }
        } else {
#pragma unroll
            for (int j = 0; j < 4; j++) if (j < m) {
                s[j] = __ldg(&eidx[base + j]); d[j] = __ldg(&eidx[E + base + j]);
            }
        }
#pragma unroll
        for (int j = 0; j < 4; j++) if (j < m) {
            int slot = atomicAdd(&d_fill[d[j]], 1);
            if (slot < BCAP) {
                d_esrc[d[j] * BCAP + slot] = s[j];
            } else {
                int o = atomicAdd(&d_ovf_cnt, 1);
                if (o < OVF_CAP) { d_ovf[2 * o] = s[j]; d_ovf[2 * o + 1] = d[j]; }
            }
        }
    } else if (branch == 1) {
        // ---------------- GEMM1 branch: h = x @ W_gat + logits + hx16 stores ----------
        int rowBase = sub * 64;
        int warpM = wid & 3, warpN = wid >> 2;
        int g = lane >> 2, tig = lane & 3;
        int r = tid >> 2, c4 = (tid & 3) << 2;
        int gr = rowBase + r;

        cp16(&u.p.a[0][r * 20 + c4], &x[(size_t)gr * DIM + c4], gr < n ? 16 : 0);
#pragma unroll
        for (int i = 0; i < 2; i++) {
            int id = tid + i * 256;
            int wr = id >> 5, wc = (id & 31) << 2;
            cp16(&u.p.w[0][wr * 136 + wc], &Wg[(size_t)wr * DIM + wc], 16);
        }
        CP_COMMIT();

        float c[8][4];
#pragma unroll
        for (int i = 0; i < 8; i++) { c[i][0] = c[i][1] = c[i][2] = c[i][3] = 0.f; }

        for (int kk = 0; kk < 8; kk++) {
            int b = kk & 1;
            if (kk < 7) {
                int krel = (kk + 1) * 16;
                cp16(&u.p.a[b ^ 1][r * 20 + c4], &x[(size_t)gr * DIM + krel + c4],
                     gr < n ? 16 : 0);
#pragma unroll
                for (int i = 0; i < 2; i++) {
                    int id = tid + i * 256;
                    int wr = id >> 5, wc = (id & 31) << 2;
                    cp16(&u.p.w[b ^ 1][wr * 136 + wc], &Wg[(size_t)(krel + wr) * DIM + wc], 16);
                }
                CP_COMMIT();
                CP_WAIT_1();
            } else {
                CP_WAIT_0();
            }
            __syncthreads();
            if (gr < n) {
                float4 v = *(float4*)&u.p.a[b][r * 20 + c4];
                __half2 p0 = __floats2half2_rn(v.x, v.y);
                __half2 p1 = __floats2half2_rn(v.z, v.w);
                uint2 q; q.x = *(unsigned*)&p0; q.y = *(unsigned*)&p1;
                int laneCol = kk * 4 + (tid & 3);
                *(uint2*)&d_hx16[(size_t)gr * 256 + laneCol * 8 + 4] = q;
            }
            mma_chunk64(u.p.a[b], u.p.w[b], c, warpM, warpN, g, tig);
            __syncthreads();
        }
        {
            int rb = warpM * 16, cb = warpN * 64;
#pragma unroll
            for (int n8 = 0; n8 < 8; n8++) {
                int cc = cb + n8 * 8 + 2 * tig;
                u.ot[(rb + g) * 132 + cc] = c[n8][0];
                u.ot[(rb + g) * 132 + cc + 1] = c[n8][1];
                u.ot[(rb + g + 8) * 132 + cc] = c[n8][2];
                u.ot[(rb + g + 8) * 132 + cc + 1] = c[n8][3];
            }
        }
        __syncthreads();
        int tx = lane, ty = wid;
        float4 as4 = *(const float4*)&att_src[tx << 2];
        float4 ad4 = *(const float4*)&att_dst[tx << 2];
#pragma unroll
        for (int r8 = 0; r8 < 8; r8++) {
            int grr = rowBase + ty * 8 + r8;
            float4 hv = *(float4*)&u.ot[(ty * 8 + r8) * 132 + (tx << 2)];
            if (grr < n) {
                __half2 p0 = __floats2half2_rn(hv.x, hv.y);
                __half2 p1 = __floats2half2_rn(hv.z, hv.w);
                uint2 q; q.x = *(unsigned*)&p0; q.y = *(unsigned*)&p1;
                *(uint2*)&d_hx16[(size_t)grr * 256 + tx * 8] = q;
            }
            float ps = hv.x * as4.x + hv.y * as4.y + hv.z * as4.z + hv.w * as4.w;
            float pd = hv.x * ad4.x + hv.y * ad4.y + hv.z * ad4.z + hv.w * ad4.w;
#pragma unroll
            for (int o = 4; o; o >>= 1) {
                ps += __shfl_xor_sync(0xffffffffu, ps, o);
                pd += __shfl_xor_sync(0xffffffffu, pd, o);
            }
            if ((tx & 7) == 0 && grr < n) {
                int hd = tx >> 3;
                d_asrc[grr * 4 + hd] = ps;
                d_adst[grr * 4 + hd] = pd;
            }
        }
    } else {
        // ---------------- prep branch: B = Wl@Wp2, C = Wr@Wp2 + I, dvec ---------------
        int pbid = sub;
        const float* Wp2 = Wp + DIM * DIM;
        if (pbid == 4) {
            int nn = tid;
            if (nn < DIM) {
                float sacc = bp[nn];
                for (int j = 0; j < DIM; j++) sacc += bl[j] * Wp2[j * DIM + nn];
                d_dvec[nn] = sacc;
            }
            return;
        }
        float* xs = u.pr.xs;   // [64][16]
        float* ws = u.pr.ws;   // [16][128]
        int tx = lane, ty = wid;
        int rowBase = pbid * 64;
        const float* A = (rowBase < 128) ? Wl : Wr;
        int aBase = (rowBase < 128) ? rowBase : rowBase - 128;
        float acc[8][4];
#pragma unroll
        for (int rr = 0; rr < 8; rr++) { acc[rr][0] = acc[rr][1] = acc[rr][2] = acc[rr][3] = 0.f; }
        for (int kk = 0; kk < 8; kk++) {
            int r = tid >> 2, k4 = (tid & 3) << 2;
            *(float4*)&xs[r * 16 + k4] =
                *(const float4*)&A[(size_t)(aBase + r) * DIM + kk * 16 + k4];
#pragma unroll
            for (int i = 0; i < 2; i++) {
                int id = tid + i * 256;
                int wr = id >> 5, wc = (id & 31) << 2;
                *(float4*)&ws[wr * 128 + wc] =
                    *(const float4*)&Wp2[(size_t)(kk * 16 + wr) * DIM + wc];
            }
            __syncthreads();
#pragma unroll
            for (int k = 0; k < 16; k++) {
                float4 b = *(float4*)&ws[k * 128 + (tx << 2)];
#pragma unroll
                for (int r8 = 0; r8 < 8; r8++) {
                    float a = xs[(ty * 8 + r8) * 16 + k];
                    acc[r8][0] += a * b.x; acc[r8][1] += a * b.y;
                    acc[r8][2] += a * b.z; acc[r8][3] += a * b.w;
                }
            }
            __syncthreads();
        }
#pragma unroll
        for (int r8 = 0; r8 < 8; r8++) {
            int vr = rowBase + ty * 8 + r8;
            int col = tx << 2;
            if (vr < 128) {
                *(float4*)&d_B[vr * DIM + col] =
                    make_float4(acc[r8][0], acc[r8][1], acc[r8][2], acc[r8][3]);
            } else {
                int rr = vr - 128;
                float4 v = make_float4(acc[r8][0], acc[r8][1], acc[r8][2], acc[r8][3]);
                if (rr >= col && rr < col + 4) {
                    if (rr == col) v.x += 1.f;
                    else if (rr == col + 1) v.y += 1.f;
                    else if (rr == col + 2) v.z += 1.f;
                    else v.w += 1.f;
                }
                *(float4*)&d_C[rr * DIM + col] = v;
            }
        }
    }
}

// ---- gather: warp per dst node (round-7 proven version, untouched) ----
__global__ __launch_bounds__(256) void k_gather(const float* __restrict__ b_gat, int n) {
    __shared__ float s_ex[8][32][4];
    int tid = threadIdx.x, lane = tid & 31, wb = tid >> 5;
    int w = (blockIdx.x * blockDim.x + tid) >> 5;
    if (w >= n) return;
    int hd = lane >> 3;
    int c = lane << 2;
    int fill = d_fill[w];
    int deg = fill < BCAP ? fill : BCAP;
    float4 ad4 = *(const float4*)&d_adst[w * 4];
    float4 g = make_float4(0.f, 0.f, 0.f, 0.f);
    float4 sa = make_float4(0.f, 0.f, 0.f, 0.f);
    float den = 0.f;
    const uint4* hx = (const uint4*)d_hx16;

    for (int base = 0; base < deg; base += 32) {
        int cnt = deg - base; if (cnt > 32) cnt = 32;
        int myS = 0;
        float4 ex4 = make_float4(0.f, 0.f, 0.f, 0.f);
        if (lane < cnt) {
            myS = d_esrc[w * BCAP + base + lane];
            float4 as = *(const float4*)&d_asrc[myS * 4];
            float e0 = as.x + ad4.x, e1 = as.y + ad4.y;
            float e2 = as.z + ad4.z, e3 = as.w + ad4.w;
            e0 = e0 > 0.f ? e0 : 0.2f * e0;
            e1 = e1 > 0.f ? e1 : 0.2f * e1;
            e2 = e2 > 0.f ? e2 : 0.2f * e2;
            e3 = e3 > 0.f ? e3 : 0.2f * e3;
            ex4 = make_float4(__expf(e0), __expf(e1), __expf(e2), __expf(e3));
        }
        *(float4*)&s_ex[wb][lane][0] = ex4;
        __syncwarp();
#pragma unroll 8
        for (int j = 0; j < cnt; j++) {
            int s = __shfl_sync(0xffffffffu, myS, j);
            float ex = s_ex[wb][j][hd];
            den += ex;
            uint4 q = __ldg(&hx[(size_t)s * 32 + lane]);
            float2 h01 = __half22float2(*(__half2*)&q.x);
            float2 h23 = __half22float2(*(__half2*)&q.y);
            float2 x01 = __half22float2(*(__half2*)&q.z);
            float2 x23 = __half22float2(*(__half2*)&q.w);
            g.x += h01.x * ex; g.y += h01.y * ex; g.z += h23.x * ex; g.w += h23.y * ex;
            sa.x += x01.x; sa.y += x01.y; sa.z += x23.x; sa.w += x23.y;
        }
        __syncwarp();
    }

    int oc = d_ovf_cnt;
    if (oc > 0) {
        if (oc > OVF_CAP) oc = OVF_CAP;
        for (int k = 0; k < oc; k++) {
            if (d_ovf[2 * k + 1] == w) {
                int s = d_ovf[2 * k];
                float asr = __ldg(&d_asrc[s * 4 + hd]);
                float adst = (hd == 0) ? ad4.x : (hd == 1) ? ad4.y : (hd == 2) ? ad4.z : ad4.w;
                float ee = asr + adst;
                ee = ee > 0.f ? ee : 0.2f * ee;
                float ex = __expf(ee);
                den += ex;
                uint4 q = __ldg(&hx[(size_t)s * 32 + lane]);
                float2 h01 = __half22float2(*(__half2*)&q.x);
                float2 h23 = __half22float2(*(__half2*)&q.y);
                float2 x01 = __half22float2(*(__half2*)&q.z);
                float2 x23 = __half22float2(*(__half2*)&q.w);
                g.x += h01.x * ex; g.y += h01.y * ex; g.z += h23.x * ex; g.w += h23.y * ex;
                sa.x += x01.x; sa.y += x01.y; sa.z += x23.x; sa.w += x23.y;
            }
        }
    }

    // self-loop (GAT only)
    {
        float asr = d_asrc[w * 4 + hd];
        float adst = (hd == 0) ? ad4.x : (hd == 1) ? ad4.y : (hd == 2) ? ad4.z : ad4.w;
        float ee = asr + adst;
        ee = ee > 0.f ? ee : 0.2f * ee;
        float exs = __expf(ee);
        den += exs;
        uint4 q = __ldg(&hx[(size_t)w * 32 + lane]);
        float2 h01 = __half22float2(*(__half2*)&q.x);
        float2 h23 = __half22float2(*(__half2*)&q.y);
        g.x += h01.x * exs; g.y += h01.y * exs; g.z += h23.x * exs; g.w += h23.y * exs;
    }

    float inv = 1.f / (den + 1e-16f);
    float4 bg = *(const float4*)&b_gat[c];
    size_t off = (size_t)w * DIM + c;
    *(float4*)&d_gacc[off] = make_float4(g.x * inv + bg.x, g.y * inv + bg.y,
                                         g.z * inv + bg.z, g.w * inv + bg.w);
    float dg = fill > 0 ? (float)fill : 1.f;
    float idg = 1.f / dg;
    *(float4*)&d_sacc[off] = make_float4(sa.x * idg, sa.y * idg, sa.z * idg, sa.w * idg);
}

// ---- final fused 3-GEMM (K=384, chunk=32, double-buffered) + LN + re-zero ----
__global__ void k_final(const float* __restrict__ x, const float* __restrict__ Wp,
                        const float* __restrict__ gamma, const float* __restrict__ beta,
                        float* __restrict__ out, int n) {
    extern __shared__ float dsm[];
    float* sa = dsm;                    // [2][64*36]
    float* sw = dsm + 2 * 64 * 36;      // [2][32*136]
    float* ot = dsm;                    // epilogue overlay [64*132]
    int tid = threadIdx.x, lane = tid & 31, wid = tid >> 5;
    int rowBase = blockIdx.x * 64;

    // re-zero scratch for the next replay
    if (tid < 64) {
        int zi = rowBase + tid;
        if (zi < n) d_fill[zi] = 0;
    }
    if (blockIdx.x == 0 && tid == 64) d_ovf_cnt = 0;

    int warpM = wid & 3, warpN = wid >> 2;
    int g = lane >> 2, tig = lane & 3;

    float c[8][4];
#pragma unroll
    for (int i = 0; i < 8; i++) { c[i][0] = c[i][1] = c[i][2] = c[i][3] = 0.f; }

    auto stage = [&](int j, int buf) {
        int seg = j >> 2;
        int krel = (j & 3) * 32;
        const float* src = (seg == 0) ? d_gacc : (seg == 1) ? d_sacc : x;
        const float* wseg = (seg == 0) ? Wp : (seg == 1) ? d_B : d_C;
#pragma unroll
        for (int i = 0; i < 2; i++) {
            int id = tid + i * 256;
            int r = id >> 3, c4 = (id & 7) << 2;
            int gr = rowBase + r;
            cp16(&sa[buf * 2304 + r * 36 + c4], &src[(size_t)gr * DIM + krel + c4],
                 gr < n ? 16 : 0);
        }
#pragma unroll
        for (int i = 0; i < 4; i++) {
            int id = tid + i * 256;
            int wr = id >> 5, wc = (id & 31) << 2;
            cp16(&sw[buf * 4352 + wr * 136 + wc], &wseg[(size_t)(krel + wr) * DIM + wc], 16);
        }
        CP_COMMIT();
    };

    stage(0, 0);

    for (int kk = 0; kk < 12; kk++) {
        int b = kk & 1;
        if (kk < 11) {
            stage(kk + 1, b ^ 1);
            CP_WAIT_1();
        } else {
            CP_WAIT_0();
        }
        __syncthreads();
        const float* A = &sa[b * 2304];
        const float* W = &sw[b * 4352];
#pragma unroll
        for (int k8 = 0; k8 < 32; k8 += 8) {
            unsigned a0 = __float_as_uint(A[(warpM * 16 + g) * 36 + k8 + tig]);
            unsigned a1 = __float_as_uint(A[(warpM * 16 + g + 8) * 36 + k8 + tig]);
            unsigned a2 = __float_as_uint(A[(warpM * 16 + g) * 36 + k8 + tig + 4]);
            unsigned a3 = __float_as_uint(A[(warpM * 16 + g + 8) * 36 + k8 + tig + 4]);
#pragma unroll
            for (int n8 = 0; n8 < 8; n8++) {
                int cb = warpN * 64 + n8 * 8 + g;
                unsigned b0 = __float_as_uint(W[(k8 + tig) * 136 + cb]);
                unsigned b1 = __float_as_uint(W[(k8 + tig + 4) * 136 + cb]);
                mma_tf32(c[n8], a0, a1, a2, a3, b0, b1);
            }
        }
        __syncthreads();
    }
    {
        int rb = warpM * 16, cb = warpN * 64;
#pragma unroll
        for (int n8 = 0; n8 < 8; n8++) {
            int cq = cb + n8 * 8 + 2 * tig;
            ot[(rb + g) * 132 + cq] = c[n8][0];     ot[(rb + g) * 132 + cq + 1] = c[n8][1];
            ot[(rb + g + 8) * 132 + cq] = c[n8][2]; ot[(rb + g + 8) * 132 + cq + 1] = c[n8][3];
        }
    }
    __syncthreads();
    int tx = lane, ty = wid;
    float4 dv = *(const float4*)&d_dvec[tx << 2];
    float4 gm = *(const float4*)&gamma[tx << 2];
    float4 bt = *(const float4*)&beta[tx << 2];
#pragma unroll
    for (int r8 = 0; r8 < 8; r8++) {
        float4 av = *(float4*)&ot[(ty * 8 + r8) * 132 + (tx << 2)];
        float v0 = av.x + dv.x, v1 = av.y + dv.y;
        float v2 = av.z + dv.z, v3 = av.w + dv.w;
        float sum = v0 + v1 + v2 + v3;
        float sq = v0 * v0 + v1 * v1 + v2 * v2 + v3 * v3;
#pragma unroll
        for (int o = 16; o; o >>= 1) {
            sum += __shfl_xor_sync(0xffffffffu, sum, o);
            sq  += __shfl_xor_sync(0xffffffffu, sq, o);
        }
        float mu = sum * (1.f / 128.f);
        float var = sq * (1.f / 128.f) - mu * mu;
        float rstd = rsqrtf(var + 1e-5f);
        int grr = rowBase + ty * 8 + r8;
        if (grr < n) {
            float4 o4;
            o4.x = (v0 - mu) * rstd * gm.x + bt.x;
            o4.y = (v1 - mu) * rstd * gm.y + bt.y;
            o4.z = (v2 - mu) * rstd * gm.z + bt.z;
            o4.w = (v3 - mu) * rstd * gm.w + bt.w;
            *(float4*)&out[(size_t)grr * DIM + (tx << 2)] = o4;
        }
    }
}

extern "C" void kernel_launch(void* const* d_in, const int* in_sizes, int n_in,
                              void* d_out, int out_size) {
    const float* x       = (const float*)d_in[0];
    const void*  eidx    = d_in[1];
    const float* W_gat   = (const float*)d_in[2];
    const float* att_src = (const float*)d_in[3];
    const float* att_dst = (const float*)d_in[4];
    const float* b_gat   = (const float*)d_in[5];
    const float* W_l     = (const float*)d_in[6];
    const float* b_l     = (const float*)d_in[7];
    const float* W_r     = (const float*)d_in[8];
    const float* W_proj  = (const float*)d_in[9];
    const float* b_proj  = (const float*)d_in[10];
    const float* gamma   = (const float*)d_in[11];
    const float* beta    = (const float*)d_in[12];

    int n = in_sizes[0] / DIM;
    int E = in_sizes[1] / 2;
    int nbG = (n + 63) / 64;
    int nbS = ((E + 3) / 4 + 255) / 256;

    const int SMEM_F = (2 * 64 * 36 + 2 * 32 * 136) * 4;   // 53,248 B
    cudaFuncSetAttribute(k_final, cudaFuncAttributeMaxDynamicSharedMemorySize, SMEM_F);

    k_fused<<<nbG + nbS + 5, 256>>>(x, W_gat, att_src, att_dst, (const int*)eidx,
                                    W_l, W_r, b_l, W_proj, b_proj, n, E, nbG, nbS); // 1
    k_gather<<<(n * 32 + 255) / 256, 256>>>(b_gat, n);                              // 2
    k_final<<<nbG, 256, SMEM_F>>>(x, W_proj, gamma, beta, (float*)d_out, n);        // 3
}